// round 7
// baseline (speedup 1.0000x reference)
#include <cuda_runtime.h>

// Problem constants (fixed by reference setup_inputs)
#define B_SZ 16
#define S_SZ 4096
#define D_SZ 512
#define PE_DIM 256
#define VEC_PER_ROW (D_SZ / 4)       // 128 float4 per (b,s) row
#define PE_VEC_PER_ROW (PE_DIM / 4)  // 64 float4 per pe row
#define ILP 8
#define TPB 256
// block = 256 threads * ILP 8 = 2048 float4 = 16 (b,s) rows per block
// 256 blocks per batch -> b = blockIdx.x >> 8 (uniform within block)

// ---------------------------------------------------------------------------
// Fused kernel: in-flight-depth version. 12 front-batched loads per thread
// (8 x-stream LDG.128 + 4 mask int4), indices recomputed inline to keep
// regs <= 64 (4 blocks/SM). L = 4096 - sum(mask), REDUX + one BAR.
// ---------------------------------------------------------------------------
__global__ void __launch_bounds__(TPB, 4) fused_pe_kernel(
    const float4* __restrict__ x,
    const int4*   __restrict__ mask,  // (16, 1024) int4
    const float4* __restrict__ pe,    // (5000, 64) float4
    float4* __restrict__ out
) {
    const int tid  = threadIdx.x;
    const int base = blockIdx.x * (TPB * ILP) + tid;
    const int b    = blockIdx.x >> 8;            // 256 blocks per batch

    // 1) Mask loads first (head of the longest dependency chain)
    const int4* m = mask + b * (S_SZ / 4);
    int4 mv[4];
    #pragma unroll
    for (int k = 0; k < 4; k++)
        mv[k] = __ldg(&m[k * TPB + tid]);

    // 2) Front-batch all x loads (independent, streaming, evict-first)
    float4 xv[ILP];
    #pragma unroll
    for (int k = 0; k < ILP; k++)
        xv[k] = __ldcs(&x[base + k * TPB]);

    // 3) Base-pe adds (indices recomputed inline; chunk4 = i&63, s = (i>>7)&4095)
    #pragma unroll
    for (int k = 0; k < ILP; k++) {
        const int i  = base + k * TPB;
        const int s  = (i >> 7) & (S_SZ - 1);
        const int c4 = i & (PE_VEC_PER_ROW - 1);
        const float4 basev = pe[s * PE_VEC_PER_ROW + c4];
        xv[k].x += basev.x;
        xv[k].y += basev.y;
        xv[k].z += basev.z;
        xv[k].w += basev.w;
    }

    // 4) L = S - sum(mask): adds + REDUX + one BAR + broadcast LDS.128
    int ones = ((mv[0].x + mv[0].y) + (mv[0].z + mv[0].w))
             + ((mv[1].x + mv[1].y) + (mv[1].z + mv[1].w))
             + ((mv[2].x + mv[2].y) + (mv[2].z + mv[2].w))
             + ((mv[3].x + mv[3].y) + (mv[3].z + mv[3].w));
    ones = __reduce_add_sync(0xFFFFFFFFu, ones);

    __shared__ __align__(16) int warp_sums[8];   // TPB/32 = 8 warps
    if ((tid & 31) == 0) warp_sums[tid >> 5] = ones;
    __syncthreads();

    const int4* ws = reinterpret_cast<const int4*>(warp_sums);
    const int4 w0 = ws[0], w1 = ws[1];
    const int L = S_SZ - (((w0.x + w0.y) + (w0.z + w0.w))
                        + ((w1.x + w1.y) + (w1.z + w1.w)));

    // 5) Reversed-feature pe + store per k (frees regs as we go)
    #pragma unroll
    for (int k = 0; k < ILP; k++) {
        const int i  = base + k * TPB;
        const int s  = (i >> 7) & (S_SZ - 1);
        const int c4 = i & (PE_VEC_PER_ROW - 1);
        if (s < L) {
            const int row = L - 1 - s;           // >= 0 because s < L
            const float4 rv = pe[row * PE_VEC_PER_ROW + (PE_VEC_PER_ROW - 1 - c4)];
            xv[k].x += rv.w;
            xv[k].y += rv.z;
            xv[k].z += rv.y;
            xv[k].w += rv.x;
        }
        __stcs(&out[i], xv[k]);
    }
}

// ---------------------------------------------------------------------------
// d_in[0] = x (f32, 16*4096*512), d_in[1] = mask (i32, 16*4096),
// d_in[2] = pe (f32, 5000*256)
// ---------------------------------------------------------------------------
extern "C" void kernel_launch(void* const* d_in, const int* in_sizes, int n_in,
                              void* d_out, int out_size) {
    const float* x    = (const float*)d_in[0];
    const int*   mask = (const int*)d_in[1];
    const float* pe   = (const float*)d_in[2];
    float* out = (float*)d_out;

    const int total_vec = B_SZ * S_SZ * VEC_PER_ROW;        // 8,388,608
    const int blocks = total_vec / (TPB * ILP);             // 4096
    fused_pe_kernel<<<blocks, TPB>>>(
        (const float4*)x, (const int4*)mask, (const float4*)pe, (float4*)out);
}